// round 1
// baseline (speedup 1.0000x reference)
#include <cuda_runtime.h>
#include <cstdint>

// Gather: out[i, :] = embedding[index[i], :],  D = 64 floats = 16 float4.
// One float4 per thread; 16 threads per row. Fully coalesced loads & stores
// (each row is 256B-aligned -> exactly 2 full 128B lines).

static constexpr int D = 64;
static constexpr int VEC_PER_ROW = D / 4;  // 16

__global__ __launch_bounds__(256) void gather_kernel(
    const float4* __restrict__ emb,   // [U, 16] as float4
    const int*    __restrict__ idx,   // [N]
    float4*       __restrict__ out,   // [N, 16] as float4
    int64_t n_vec)                    // N * 16
{
    int64_t gid = (int64_t)blockIdx.x * blockDim.x + threadIdx.x;
    if (gid >= n_vec) return;
    int64_t row = gid >> 4;           // gid / 16
    int     seg = (int)(gid & 15);    // gid % 16
    int64_t src_row = (int64_t)__ldg(&idx[row]);
    // streaming store: output is write-once, don't pollute L2 needed for
    // embedding reuse
    float4 v = __ldg(&emb[src_row * VEC_PER_ROW + seg]);
    __stcs(&out[gid], v);
}

extern "C" void kernel_launch(void* const* d_in, const int* in_sizes, int n_in,
                              void* d_out, int out_size) {
    const float4* emb = (const float4*)d_in[0];  // embedding [U, 64] f32
    const int*    idx = (const int*)d_in[1];     // index [N] i32
    float4*       out = (float4*)d_out;

    int64_t n = in_sizes[1];              // N = 2097152
    int64_t n_vec = n * VEC_PER_ROW;      // total float4s to move

    int threads = 256;
    int64_t blocks = (n_vec + threads - 1) / threads;
    gather_kernel<<<(unsigned)blocks, threads>>>(emb, idx, out, n_vec);
}

// round 2
// speedup vs baseline: 1.2840x; 1.2840x over previous
#include <cuda_runtime.h>
#include <cstdint>

// Gather: out[i, :] = embedding[index[i], :],  D = 64 floats = 16 float4.
// 16 threads per row, one float4 each (rows are 256B-aligned -> 2 full lines).
// UNROLL=4 independent gathers per thread, front-batched loads for MLP.

static constexpr int D = 64;
static constexpr int VEC_PER_ROW = D / 4;  // 16
static constexpr int UNROLL = 4;

__global__ __launch_bounds__(256) void gather_kernel(
    const float4* __restrict__ emb,   // [U, 16] as float4
    const int*    __restrict__ idx,   // [N]
    float4*       __restrict__ out,   // [N, 16] as float4
    int64_t n_vec)                    // N * 16
{
    const int64_t stride = (int64_t)gridDim.x * blockDim.x;   // threads total
    int64_t g = (int64_t)blockIdx.x * blockDim.x + threadIdx.x;

    // Main unrolled body: 4 independent gathers, batched loads.
    // n_vec is a multiple of 16; grid sized so full UNROLL batches dominate.
    while (g + (UNROLL - 1) * stride < n_vec) {
        int64_t gg[UNROLL];
        int     src[UNROLL];
#pragma unroll
        for (int u = 0; u < UNROLL; u++) {
            gg[u] = g + u * stride;
            src[u] = __ldg(&idx[gg[u] >> 4]);
        }
        float4 v[UNROLL];
#pragma unroll
        for (int u = 0; u < UNROLL; u++) {
            int seg = (int)(gg[u] & 15);
            v[u] = __ldg(&emb[(int64_t)src[u] * VEC_PER_ROW + seg]);
        }
#pragma unroll
        for (int u = 0; u < UNROLL; u++) {
            __stcs(&out[gg[u]], v[u]);
        }
        g += UNROLL * stride;
    }
    // Tail
    while (g < n_vec) {
        int src = __ldg(&idx[g >> 4]);
        int seg = (int)(g & 15);
        float4 v = __ldg(&emb[(int64_t)src * VEC_PER_ROW + seg]);
        __stcs(&out[g], v);
        g += stride;
    }
}

extern "C" void kernel_launch(void* const* d_in, const int* in_sizes, int n_in,
                              void* d_out, int out_size) {
    const float4* emb = (const float4*)d_in[0];  // embedding [U, 64] f32
    const int*    idx = (const int*)d_in[1];     // index [N] i32
    float4*       out = (float4*)d_out;

    int64_t n = in_sizes[1];              // N = 2097152
    int64_t n_vec = n * VEC_PER_ROW;      // 33,554,432 float4s

    const int threads = 256;
    // Size grid so each thread does exactly UNROLL iterations when n_vec
    // divides evenly (it does: 33554432 / (256*4) = 32768 blocks).
    int64_t blocks = (n_vec + (int64_t)threads * UNROLL - 1) /
                     ((int64_t)threads * UNROLL);
    gather_kernel<<<(unsigned)blocks, threads>>>(emb, idx, out, n_vec);
}

// round 5
// speedup vs baseline: 1.2848x; 1.0006x over previous
#include <cuda_runtime.h>
#include <cstdint>

// Gather: out[i, :] = embedding[index[i], :],  D = 64 floats = 16 float4.
// 16 threads/row, one float4 each. UNROLL=4 front-batched gathers for MLP.
// L2 steering via createpolicy + ld.global.nc.L2::cache_hint:
//   embedding = evict_last (keep table resident),
//   index     = evict_first (streamed once),
//   output    = st.global.cs (evict-first write stream).

static constexpr int D = 64;
static constexpr int VEC_PER_ROW = D / 4;  // 16
static constexpr int UNROLL = 4;

__device__ __forceinline__ float4 ldg_emb(const float4* p, uint64_t pol) {
    float4 v;
    asm("ld.global.nc.L2::cache_hint.v4.f32 {%0,%1,%2,%3}, [%4], %5;"
        : "=f"(v.x), "=f"(v.y), "=f"(v.z), "=f"(v.w)
        : "l"(p), "l"(pol));
    return v;
}

__device__ __forceinline__ int ldg_idx(const int* p, uint64_t pol) {
    int v;
    asm("ld.global.nc.L2::cache_hint.b32 %0, [%1], %2;"
        : "=r"(v)
        : "l"(p), "l"(pol));
    return v;
}

__global__ __launch_bounds__(256) void gather_kernel(
    const float4* __restrict__ emb,   // [U, 16] as float4
    const int*    __restrict__ idx,   // [N]
    float4*       __restrict__ out,   // [N, 16] as float4
    int64_t n_vec)                    // N * 16
{
    uint64_t pol_last, pol_first;
    asm("createpolicy.fractional.L2::evict_last.b64 %0, 1.0;"  : "=l"(pol_last));
    asm("createpolicy.fractional.L2::evict_first.b64 %0, 1.0;" : "=l"(pol_first));

    const int64_t stride = (int64_t)gridDim.x * blockDim.x;
    int64_t g = (int64_t)blockIdx.x * blockDim.x + threadIdx.x;

    while (g + (UNROLL - 1) * stride < n_vec) {
        int64_t gg[UNROLL];
        int     src[UNROLL];
#pragma unroll
        for (int u = 0; u < UNROLL; u++) {
            gg[u] = g + u * stride;
            src[u] = ldg_idx(&idx[gg[u] >> 4], pol_first);
        }
        float4 v[UNROLL];
#pragma unroll
        for (int u = 0; u < UNROLL; u++) {
            int seg = (int)(gg[u] & 15);
            v[u] = ldg_emb(&emb[(int64_t)src[u] * VEC_PER_ROW + seg], pol_last);
        }
#pragma unroll
        for (int u = 0; u < UNROLL; u++) {
            __stcs(&out[gg[u]], v[u]);
        }
        g += UNROLL * stride;
    }
    while (g < n_vec) {
        int src = ldg_idx(&idx[g >> 4], pol_first);
        int seg = (int)(g & 15);
        float4 v = ldg_emb(&emb[(int64_t)src * VEC_PER_ROW + seg], pol_last);
        __stcs(&out[g], v);
        g += stride;
    }
}

extern "C" void kernel_launch(void* const* d_in, const int* in_sizes, int n_in,
                              void* d_out, int out_size) {
    const float4* emb = (const float4*)d_in[0];  // embedding [U, 64] f32
    const int*    idx = (const int*)d_in[1];     // index [N] i32
    float4*       out = (float4*)d_out;

    int64_t n = in_sizes[1];              // N = 2097152
    int64_t n_vec = n * VEC_PER_ROW;      // 33,554,432 float4s

    const int threads = 256;
    int64_t blocks = (n_vec + (int64_t)threads * UNROLL - 1) /
                     ((int64_t)threads * UNROLL);   // 32768
    gather_kernel<<<(unsigned)blocks, threads>>>(emb, idx, out, n_vec);
}